// round 5
// baseline (speedup 1.0000x reference)
#include <cuda_runtime.h>
#include <cuda_bf16.h>
#include <cstdint>
#include <cstddef>

// Problem constants
#define BB 2
#define TT 2048
#define CC 2048
#define HH 16
#define DH 128
#define M_ROWS (BB*TT)          // 4096
#define QKV_N  (3*CC)           // 6144

// Scratch (allocation-free rule: __device__ globals)
__device__ float g_qkv[(size_t)M_ROWS * QKV_N];   // 96 MB
__device__ float g_y  [(size_t)M_ROWS * CC];      // 32 MB (tf32-rounded)
__device__ float g_xt [(size_t)M_ROWS * CC];      // 32 MB x pre-rounded
__device__ float g_wat[(size_t)CC * QKV_N];       // 48 MB W_attn pre-rounded
__device__ float g_wpt[(size_t)CC * CC];          // 16 MB W_proj pre-rounded

// ---------------------------------------------------------------------------
// tf32 helpers (plain sm_80+ PTX)
// ---------------------------------------------------------------------------
__device__ __forceinline__ float f2tf32f(float x) {
    uint32_t o;
    asm("cvt.rna.tf32.f32 %0, %1;" : "=r"(o) : "f"(x));
    return __uint_as_float(o);
}

__device__ __forceinline__ void mma16n8k8(float* c, const float* a, const float* b) {
    const uint32_t* A = reinterpret_cast<const uint32_t*>(a);
    const uint32_t* B = reinterpret_cast<const uint32_t*>(b);
    asm volatile(
        "mma.sync.aligned.m16n8k8.row.col.f32.tf32.tf32.f32 "
        "{%0,%1,%2,%3}, {%4,%5,%6,%7}, {%8,%9}, {%0,%1,%2,%3};"
        : "+f"(c[0]), "+f"(c[1]), "+f"(c[2]), "+f"(c[3])
        : "r"(A[0]), "r"(A[1]), "r"(A[2]), "r"(A[3]), "r"(B[0]), "r"(B[1]));
}

// ---------------------------------------------------------------------------
// One-time tf32 pre-rounding: out[i] = round_tf32(in[i])
// ---------------------------------------------------------------------------
__global__ __launch_bounds__(256)
void round_tf32_kernel(const float* __restrict__ in, float* __restrict__ out) {
    size_t i = (size_t)blockIdx.x * 256 + threadIdx.x;
    float4 v = ((const float4*)in)[i];
    float4 t;
    t.x = f2tf32f(v.x); t.y = f2tf32f(v.y);
    t.z = f2tf32f(v.z); t.w = f2tf32f(v.w);
    ((float4*)out)[i] = t;
}

// ---------------------------------------------------------------------------
// tf32 mma.sync GEMM:  C[M,N] = A[M,K] @ W[K,N] + bias[N]
// Inputs A, W must be pre-rounded to tf32. BM=128, BN=256, BK=32.
// 512 threads = 16 warps (4m x 4n), warp tile 32x64.
// Fragment-major smem: A frag = 1 LDS.128, B frag = 1 LDS.64, conflict-free.
//   A elem (r,k): rb=r>>4, g=r&7, u=(r>>3)&1, s=k>>3, tg=k&3, v=(k>>2)&1
//     addrA = (rb*4+s)*128 + (g*4+tg)*4 + u + 2v        (4096 floats)
//   B elem (k,n): nb=n>>3, g=n&7, s=k>>3, tg=k&3, v=(k>>2)&1
//     addrB = (nb*4+s)*64 + (g*4+tg)*2 + v              (8192 floats)
// Optional fused cache store for col >= CC.
// ---------------------------------------------------------------------------
#define GBM 128
#define GBN 256
#define GBK 32
#define A_TILE 4096
#define B_TILE 8192
#define GEMM_SMEM ((2 * A_TILE + 2 * B_TILE) * 4)   // 98304 B

__global__ __launch_bounds__(512)
void tf32_gemm_kernel(const float* __restrict__ A, const float* __restrict__ W,
                      const float* __restrict__ bias, float* __restrict__ C,
                      float* __restrict__ cache,
                      int M, int N, int K) {
    extern __shared__ float sm[];
    float* As = sm;                     // [2][4096]
    float* Bs = sm + 2 * A_TILE;        // [2][8192]

    const int tid  = threadIdx.x;
    const int wid  = tid >> 5;
    const int lane = tid & 31;
    const int g    = lane >> 2;
    const int tg   = lane & 3;
    const int wmb  = (wid & 3) * 2;     // warp A row-block base (rb units of 16)
    const int wnb  = (wid >> 2) * 8;    // warp B col-block base (nb units of 8)
    const int m0   = blockIdx.y * GBM;
    const int n0   = blockIdx.x * GBN;

    // Global load + frag-major smem store coordinates
    const float* gA[2];  int sA[2];
#pragma unroll
    for (int i = 0; i < 2; i++) {
        int idx = i * 512 + tid;
        int rA = idx >> 3, cA = idx & 7;
        gA[i] = A + (size_t)(m0 + rA) * K + cA * 4;
        sA[i] = ((rA >> 4) * 4 + (cA >> 1)) * 128 + (rA & 7) * 16
              + ((rA >> 3) & 1) + 2 * (cA & 1);
    }
    const float* gB[4];  int sB[4];
#pragma unroll
    for (int i = 0; i < 4; i++) {
        int idx = i * 512 + tid;
        int rB = idx >> 6, cB = idx & 63;
        gB[i] = W + (size_t)rB * N + n0 + cB * 4;
        sB[i] = (cB >> 1) * 256 + (rB >> 3) * 64 + (cB & 1) * 32
              + (rB & 3) * 2 + ((rB >> 2) & 1);
    }

    float c[2][8][4];
#pragma unroll
    for (int i = 0; i < 2; i++)
#pragma unroll
        for (int j = 0; j < 8; j++)
#pragma unroll
            for (int q = 0; q < 4; q++) c[i][j][q] = 0.0f;

    const int NC = K / GBK;   // 64
    float4 va[2], vb[4];

    // ---- prologue: chunk 0 ----
#pragma unroll
    for (int i = 0; i < 2; i++) va[i] = *(const float4*)gA[i];
#pragma unroll
    for (int i = 0; i < 4; i++) vb[i] = *(const float4*)gB[i];
#pragma unroll
    for (int i = 0; i < 2; i++) {
        As[sA[i]]      = va[i].x;
        As[sA[i] + 4]  = va[i].y;
        As[sA[i] + 8]  = va[i].z;
        As[sA[i] + 12] = va[i].w;
    }
#pragma unroll
    for (int i = 0; i < 4; i++) {
        Bs[sB[i]]      = vb[i].x;
        Bs[sB[i] + 8]  = vb[i].y;
        Bs[sB[i] + 16] = vb[i].z;
        Bs[sB[i] + 24] = vb[i].w;
    }
    __syncthreads();

    for (int ch = 0; ch < NC; ++ch) {
        const int buf = ch & 1;
        const float* Ab = As + buf * A_TILE;
        const float* Bb = Bs + buf * B_TILE;

        if (ch + 1 < NC) {
            const int ka = (ch + 1) * GBK;
            const size_t kb = (size_t)(ch + 1) * GBK * N;
#pragma unroll
            for (int i = 0; i < 2; i++) va[i] = *(const float4*)(gA[i] + ka);
#pragma unroll
            for (int i = 0; i < 4; i++) vb[i] = *(const float4*)(gB[i] + kb);
        }

#pragma unroll
        for (int s = 0; s < 4; s++) {
            float4 a0 = *(const float4*)&Ab[((wmb + 0) * 4 + s) * 128 + lane * 4];
            float4 a1 = *(const float4*)&Ab[((wmb + 1) * 4 + s) * 128 + lane * 4];
#pragma unroll
            for (int j = 0; j < 8; j++) {
                float2 bb = *(const float2*)&Bb[((wnb + j) * 4 + s) * 64 + lane * 2];
                mma16n8k8(c[0][j], (const float*)&a0, (const float*)&bb);
                mma16n8k8(c[1][j], (const float*)&a1, (const float*)&bb);
            }
        }
        __syncthreads();

        if (ch + 1 < NC) {
            float* An = As + (buf ^ 1) * A_TILE;
            float* Bn = Bs + (buf ^ 1) * B_TILE;
#pragma unroll
            for (int i = 0; i < 2; i++) {
                An[sA[i]]      = va[i].x;
                An[sA[i] + 4]  = va[i].y;
                An[sA[i] + 8]  = va[i].z;
                An[sA[i] + 12] = va[i].w;
            }
#pragma unroll
            for (int i = 0; i < 4; i++) {
                Bn[sB[i]]      = vb[i].x;
                Bn[sB[i] + 8]  = vb[i].y;
                Bn[sB[i] + 16] = vb[i].z;
                Bn[sB[i] + 24] = vb[i].w;
            }
            __syncthreads();
        }
    }

    // ---- epilogue: bias add, direct stores (+ optional fused cache store) ----
#pragma unroll
    for (int i = 0; i < 2; i++) {
        int row = m0 + (wmb + i) * 16 + g;
#pragma unroll
        for (int j = 0; j < 8; j++) {
            int col = n0 + (wnb + j) * 8 + 2 * tg;
            float2 bv = *(const float2*)(bias + col);
            float2 o0, o1;
            o0.x = c[i][j][0] + bv.x;  o0.y = c[i][j][1] + bv.y;
            o1.x = c[i][j][2] + bv.x;  o1.y = c[i][j][3] + bv.y;
            *(float2*)(C + (size_t)row * N + col) = o0;
            *(float2*)(C + (size_t)(row + 8) * N + col) = o1;
            if (cache != nullptr && col >= CC) {
                int cc = col - CC;
                *(float2*)(cache + (size_t)row * (2 * CC) + cc) = o0;
                *(float2*)(cache + (size_t)(row + 8) * (2 * CC) + cc) = o1;
            }
        }
    }
}

// ---------------------------------------------------------------------------
// Flash attention with tf32 mma.sync (causal). Same as R4, but writes its
// output pre-rounded to tf32 (consumed only by the proj GEMM).
// ---------------------------------------------------------------------------
#define AQP 132
#define AKP 132
#define APP 68
#define ATTN_SMEM_FLOATS (128*AQP + 64*AKP + 64*AKP + 128*APP)
#define ATTN_SMEM_BYTES  (ATTN_SMEM_FLOATS * 4)

__global__ __launch_bounds__(256)
void attn_mma_kernel(const float* __restrict__ qkv, float* __restrict__ y) {
    extern __shared__ float sm[];
    float* Qs = sm;                       // [128][132]
    float* Ks = Qs + 128 * AQP;           // [64][132]
    float* Vs = Ks + 64 * AKP;            // [64][132]
    float* Ps = Vs + 64 * AKP;            // [128][68]

    const int tid  = threadIdx.x;
    const int wid  = tid >> 5;
    const int lane = tid & 31;
    const int g    = lane >> 2;
    const int tg   = lane & 3;
    const int bh   = blockIdx.x;
    const int b    = bh >> 4;
    const int h    = bh & 15;
    const int qt   = gridDim.y - 1 - blockIdx.y;
    const int q0   = qt * 128;
    const int wr0  = wid * 16;

    const float SCALE = 0.08838834764831845f;
    const size_t RS = (size_t)QKV_N;

    const float* qbase = qkv + (size_t)b * TT * RS + (size_t)h * DH;
    const float* kbase = qbase + CC;
    const float* vbase = qbase + 2 * CC;

    for (int i = tid; i < 128 * 32; i += 256) {
        int r = i >> 5, dv = i & 31;
        float4 v = *(const float4*)(qbase + (size_t)(q0 + r) * RS + dv * 4);
        float4 t;
        t.x = f2tf32f(v.x); t.y = f2tf32f(v.y);
        t.z = f2tf32f(v.z); t.w = f2tf32f(v.w);
        *(float4*)&Qs[r * AQP + dv * 4] = t;
    }

    float m_prev[2] = {-1e30f, -1e30f};
    float l_acc[2]  = {0.0f, 0.0f};
    float acc[16][4];
#pragma unroll
    for (int nj = 0; nj < 16; nj++)
#pragma unroll
        for (int q = 0; q < 4; q++) acc[nj][q] = 0.0f;

    const int ntiles = 2 * qt + 2;

    for (int kt = 0; kt < ntiles; ++kt) {
        const int k0 = kt * 64;
        __syncthreads();

        for (int i = tid; i < 64 * 32; i += 256) {
            int r = i >> 5, dv = i & 31;
            float4 kv = *(const float4*)(kbase + (size_t)(k0 + r) * RS + dv * 4);
            float4 vv = *(const float4*)(vbase + (size_t)(k0 + r) * RS + dv * 4);
            float4 t;
            t.x = f2tf32f(kv.x); t.y = f2tf32f(kv.y);
            t.z = f2tf32f(kv.z); t.w = f2tf32f(kv.w);
            *(float4*)&Ks[r * AKP + dv * 4] = t;
            t.x = f2tf32f(vv.x); t.y = f2tf32f(vv.y);
            t.z = f2tf32f(vv.z); t.w = f2tf32f(vv.w);
            *(float4*)&Vs[r * AKP + dv * 4] = t;
        }
        __syncthreads();

        float cs[8][4];
#pragma unroll
        for (int j = 0; j < 8; j++)
#pragma unroll
            for (int q = 0; q < 4; q++) cs[j][q] = 0.0f;

#pragma unroll
        for (int ks = 0; ks < 128; ks += 8) {
            float a[4];
            a[0] = Qs[(wr0 + g)     * AQP + ks + tg];
            a[1] = Qs[(wr0 + g + 8) * AQP + ks + tg];
            a[2] = Qs[(wr0 + g)     * AQP + ks + tg + 4];
            a[3] = Qs[(wr0 + g + 8) * AQP + ks + tg + 4];
#pragma unroll
            for (int j = 0; j < 8; j++) {
                float bb[2];
                bb[0] = Ks[(8 * j + g) * AKP + ks + tg];
                bb[1] = Ks[(8 * j + g) * AKP + ks + tg + 4];
                mma16n8k8(cs[j], a, bb);
            }
        }

        const int gr0 = q0 + wr0 + g;
        const int gr1 = gr0 + 8;
        float mx0 = -1e30f, mx1 = -1e30f;
#pragma unroll
        for (int j = 0; j < 8; j++) {
            int gc0 = k0 + 8 * j + 2 * tg;
            int gc1 = gc0 + 1;
            float s0 = cs[j][0] * SCALE; if (gc0 > gr0) s0 = -1e30f;
            float s1 = cs[j][1] * SCALE; if (gc1 > gr0) s1 = -1e30f;
            float s2 = cs[j][2] * SCALE; if (gc0 > gr1) s2 = -1e30f;
            float s3 = cs[j][3] * SCALE; if (gc1 > gr1) s3 = -1e30f;
            cs[j][0] = s0; cs[j][1] = s1; cs[j][2] = s2; cs[j][3] = s3;
            mx0 = fmaxf(mx0, fmaxf(s0, s1));
            mx1 = fmaxf(mx1, fmaxf(s2, s3));
        }
        mx0 = fmaxf(mx0, __shfl_xor_sync(0xffffffffu, mx0, 1));
        mx0 = fmaxf(mx0, __shfl_xor_sync(0xffffffffu, mx0, 2));
        mx1 = fmaxf(mx1, __shfl_xor_sync(0xffffffffu, mx1, 1));
        mx1 = fmaxf(mx1, __shfl_xor_sync(0xffffffffu, mx1, 2));

        float mn0 = fmaxf(m_prev[0], mx0);
        float mn1 = fmaxf(m_prev[1], mx1);
        float f0 = __expf(m_prev[0] - mn0);
        float f1 = __expf(m_prev[1] - mn1);
        m_prev[0] = mn0; m_prev[1] = mn1;

        float ls0 = 0.0f, ls1 = 0.0f;
#pragma unroll
        for (int j = 0; j < 8; j++) {
            float p0 = __expf(cs[j][0] - mn0);
            float p1 = __expf(cs[j][1] - mn0);
            float p2 = __expf(cs[j][2] - mn1);
            float p3 = __expf(cs[j][3] - mn1);
            ls0 += p0 + p1;
            ls1 += p2 + p3;
            float2 w0 = make_float2(f2tf32f(p0), f2tf32f(p1));
            float2 w1 = make_float2(f2tf32f(p2), f2tf32f(p3));
            *(float2*)&Ps[(wr0 + g)     * APP + 8 * j + 2 * tg] = w0;
            *(float2*)&Ps[(wr0 + g + 8) * APP + 8 * j + 2 * tg] = w1;
        }
        ls0 += __shfl_xor_sync(0xffffffffu, ls0, 1);
        ls0 += __shfl_xor_sync(0xffffffffu, ls0, 2);
        ls1 += __shfl_xor_sync(0xffffffffu, ls1, 1);
        ls1 += __shfl_xor_sync(0xffffffffu, ls1, 2);
        l_acc[0] = l_acc[0] * f0 + ls0;
        l_acc[1] = l_acc[1] * f1 + ls1;

#pragma unroll
        for (int nj = 0; nj < 16; nj++) {
            acc[nj][0] *= f0; acc[nj][1] *= f0;
            acc[nj][2] *= f1; acc[nj][3] *= f1;
        }
        __syncwarp();

#pragma unroll
        for (int ks = 0; ks < 64; ks += 8) {
            float a[4];
            a[0] = Ps[(wr0 + g)     * APP + ks + tg];
            a[1] = Ps[(wr0 + g + 8) * APP + ks + tg];
            a[2] = Ps[(wr0 + g)     * APP + ks + tg + 4];
            a[3] = Ps[(wr0 + g + 8) * APP + ks + tg + 4];
#pragma unroll
            for (int nj = 0; nj < 16; nj++) {
                float bb[2];
                bb[0] = Vs[(ks + tg)     * AKP + 8 * nj + g];
                bb[1] = Vs[(ks + tg + 4) * AKP + 8 * nj + g];
                mma16n8k8(acc[nj], a, bb);
            }
        }
        __syncwarp();
    }

    // normalize + tf32-round + write (consumed only by proj GEMM)
    float inv0 = 1.0f / l_acc[0];
    float inv1 = 1.0f / l_acc[1];
    size_t row0 = (size_t)(b * TT + q0 + wr0 + g);
    size_t row1 = row0 + 8;
#pragma unroll
    for (int nj = 0; nj < 16; nj++) {
        int col = h * DH + 8 * nj + 2 * tg;
        float2 o0 = make_float2(f2tf32f(acc[nj][0] * inv0), f2tf32f(acc[nj][1] * inv0));
        float2 o1 = make_float2(f2tf32f(acc[nj][2] * inv1), f2tf32f(acc[nj][3] * inv1));
        *(float2*)(y + row0 * CC + col) = o0;
        *(float2*)(y + row1 * CC + col) = o1;
    }
}

// ---------------------------------------------------------------------------
extern "C" void kernel_launch(void* const* d_in, const int* in_sizes, int n_in,
                              void* d_out, int out_size) {
    (void)in_sizes; (void)n_in; (void)out_size;
    const float* x      = (const float*)d_in[0];
    const float* W_attn = (const float*)d_in[2];
    const float* b_attn = (const float*)d_in[3];
    const float* W_proj = (const float*)d_in[4];
    const float* b_proj = (const float*)d_in[5];

    float* out   = (float*)d_out;
    float* y_out = out;
    float* cache = out + (size_t)M_ROWS * CC;

    float *qkv = nullptr, *yb = nullptr, *xt = nullptr, *wat = nullptr, *wpt = nullptr;
    cudaGetSymbolAddress((void**)&qkv, g_qkv);
    cudaGetSymbolAddress((void**)&yb,  g_y);
    cudaGetSymbolAddress((void**)&xt,  g_xt);
    cudaGetSymbolAddress((void**)&wat, g_wat);
    cudaGetSymbolAddress((void**)&wpt, g_wpt);

    cudaFuncSetAttribute(attn_mma_kernel,
                         cudaFuncAttributeMaxDynamicSharedMemorySize,
                         ATTN_SMEM_BYTES);
    cudaFuncSetAttribute(tf32_gemm_kernel,
                         cudaFuncAttributeMaxDynamicSharedMemorySize,
                         GEMM_SMEM);

    // 0) pre-round inputs to tf32 (one pass each)
    round_tf32_kernel<<<(int)((size_t)M_ROWS * CC / 4 / 256), 256>>>(x, xt);
    round_tf32_kernel<<<(int)((size_t)CC * QKV_N / 4 / 256), 256>>>(W_attn, wat);
    round_tf32_kernel<<<(int)((size_t)CC * CC / 4 / 256), 256>>>(W_proj, wpt);

    // 1) qkv = x @ W_attn + b_attn  (fused cache store for cols >= 2048)
    {
        dim3 grid(QKV_N / GBN, M_ROWS / GBM);   // (24, 32)
        tf32_gemm_kernel<<<grid, 512, GEMM_SMEM>>>(xt, wat, b_attn, qkv,
                                                   cache, M_ROWS, QKV_N, CC);
    }
    // 2) flash attention (tf32 mma), writes rounded y
    {
        dim3 grid(BB * HH, TT / 128);           // (32, 16)
        attn_mma_kernel<<<grid, 256, ATTN_SMEM_BYTES>>>(qkv, yb);
    }
    // 3) y = attn_out @ W_proj + b_proj
    {
        dim3 grid(CC / GBN, M_ROWS / GBM);      // (8, 32)
        tf32_gemm_kernel<<<grid, 512, GEMM_SMEM>>>(yb, wpt, b_proj, y_out,
                                                   nullptr, M_ROWS, CC, CC);
    }
}

// round 6
// speedup vs baseline: 4.5087x; 4.5087x over previous
#include <cuda_runtime.h>
#include <cuda_fp16.h>
#include <cstdint>
#include <cstddef>

// Problem constants
#define BB 2
#define TT 2048
#define CC 2048
#define HH 16
#define DH 128
#define M_ROWS (BB*TT)          // 4096
#define QKV_N  (3*CC)           // 6144

// Scratch (allocation-free rule: __device__ globals)
__device__ __half g_xh  [(size_t)M_ROWS * CC];      // x fp16        16 MB
__device__ __half g_qkvh[(size_t)M_ROWS * QKV_N];   // qkv fp16      48 MB
__device__ __half g_yh  [(size_t)M_ROWS * CC];      // attn out fp16 16 MB
__device__ __half g_wath[(size_t)QKV_N * CC];       // W_attn^T fp16 24 MB
__device__ __half g_wpth[(size_t)CC * CC];          // W_proj^T fp16  8 MB

// ---------------------------------------------------------------------------
// fp16 MMA m16n8k16 (f32 accumulate), plain sm_80+ PTX
// ---------------------------------------------------------------------------
__device__ __forceinline__ void mma_h(float* c, const uint32_t* a, const uint32_t* b) {
    asm volatile(
        "mma.sync.aligned.m16n8k16.row.col.f32.f16.f16.f32 "
        "{%0,%1,%2,%3}, {%4,%5,%6,%7}, {%8,%9}, {%0,%1,%2,%3};"
        : "+f"(c[0]), "+f"(c[1]), "+f"(c[2]), "+f"(c[3])
        : "r"(a[0]), "r"(a[1]), "r"(a[2]), "r"(a[3]), "r"(b[0]), "r"(b[1]));
}

__device__ __forceinline__ uint32_t pack_h2(float lo, float hi) {
    __half2 h = __floats2half2_rn(lo, hi);
    return *(uint32_t*)&h;
}

// ---------------------------------------------------------------------------
// Pre-pass: f32 -> f16 convert
// ---------------------------------------------------------------------------
__global__ __launch_bounds__(256)
void f2h_kernel(const float* __restrict__ in, __half* __restrict__ out) {
    size_t i = (size_t)blockIdx.x * 256 + threadIdx.x;
    float4 v = ((const float4*)in)[i];
    uint2 o;
    o.x = pack_h2(v.x, v.y);
    o.y = pack_h2(v.z, v.w);
    ((uint2*)out)[i] = o;
}

// ---------------------------------------------------------------------------
// Pre-pass: transpose + convert: in [R][Cn] f32 -> out [Cn][R] f16
// ---------------------------------------------------------------------------
__global__ void trans_h_kernel(const float* __restrict__ in, __half* __restrict__ out,
                               int R, int Cn) {
    __shared__ float t[32][33];
    int bx = blockIdx.x * 32, by = blockIdx.y * 32;
    int tx = threadIdx.x, ty = threadIdx.y;   // (32, 8)
#pragma unroll
    for (int j = 0; j < 32; j += 8)
        t[ty + j][tx] = in[(size_t)(by + ty + j) * Cn + bx + tx];
    __syncthreads();
#pragma unroll
    for (int j = 0; j < 32; j += 8)
        out[(size_t)(bx + ty + j) * R + by + tx] = __float2half_rn(t[tx][ty + j]);
}

// ---------------------------------------------------------------------------
// fp16 GEMM:  C[M,N] = A[M,K]h @ Bt[N,K]h^T + bias[N]
// BM=BN=128, BK=32 halfs. 256 threads, 8 warps (4m x 2n), warp tile 32x64.
// ---------------------------------------------------------------------------
#define GBM 128
#define GBN 128
#define GBK 32
#define GROW 20
#define G_TILE (128 * GROW)
#define GEMM_SMEM (4 * G_TILE * 4)       // 40960 B

__global__ __launch_bounds__(256, 2)
void h_gemm_kernel(const __half* __restrict__ A, const __half* __restrict__ Bt,
                   const float* __restrict__ bias,
                   float* __restrict__ Cf, __half* __restrict__ Ch,
                   float* __restrict__ cache,
                   int M, int N, int K) {
    extern __shared__ uint32_t smu[];
    uint32_t* As = smu;
    uint32_t* Bs = smu + 2 * G_TILE;

    const int tid  = threadIdx.x;
    const int wid  = tid >> 5;
    const int lane = tid & 31;
    const int g    = lane >> 2;
    const int tg   = lane & 3;
    const int wm   = (wid & 3) * 32;
    const int wn   = (wid >> 2) * 64;
    const int m0   = blockIdx.y * GBM;
    const int n0   = blockIdx.x * GBN;
    const int rowu4 = K / 8;

    const uint4* gA[2]; const uint4* gB[2]; int sAo[2];
#pragma unroll
    for (int i = 0; i < 2; i++) {
        int idx = i * 256 + tid;
        int r = idx >> 2, c4 = idx & 3;
        gA[i] = (const uint4*)A + (size_t)(m0 + r) * rowu4 + c4;
        gB[i] = (const uint4*)Bt + (size_t)(n0 + r) * rowu4 + c4;
        sAo[i] = r * GROW + c4 * 4;
    }

    float c[2][8][4];
#pragma unroll
    for (int i = 0; i < 2; i++)
#pragma unroll
        for (int j = 0; j < 8; j++)
#pragma unroll
            for (int q = 0; q < 4; q++) c[i][j][q] = 0.0f;

    const int NC = K / GBK;   // 64
    uint4 va[2], vb[2];

#pragma unroll
    for (int i = 0; i < 2; i++) { va[i] = gA[i][0]; vb[i] = gB[i][0]; }
#pragma unroll
    for (int i = 0; i < 2; i++) {
        *(uint4*)&As[sAo[i]] = va[i];
        *(uint4*)&Bs[sAo[i]] = vb[i];
    }
    __syncthreads();

    for (int ch = 0; ch < NC; ++ch) {
        const int buf = ch & 1;
        const uint32_t* Ab = As + buf * G_TILE;
        const uint32_t* Bb = Bs + buf * G_TILE;

        if (ch + 1 < NC) {
            int o = (ch + 1) * 4;
#pragma unroll
            for (int i = 0; i < 2; i++) { va[i] = gA[i][o]; vb[i] = gB[i][o]; }
        }

#pragma unroll
        for (int s = 0; s < 2; s++) {
            uint32_t af[2][4];
#pragma unroll
            for (int i = 0; i < 2; i++) {
                int r = wm + 16 * i + g;
                af[i][0] = Ab[(r)     * GROW + s * 8 + tg];
                af[i][1] = Ab[(r + 8) * GROW + s * 8 + tg];
                af[i][2] = Ab[(r)     * GROW + s * 8 + tg + 4];
                af[i][3] = Ab[(r + 8) * GROW + s * 8 + tg + 4];
            }
#pragma unroll
            for (int j = 0; j < 8; j++) {
                int cn = wn + 8 * j + g;
                uint32_t bf[2];
                bf[0] = Bb[cn * GROW + s * 8 + tg];
                bf[1] = Bb[cn * GROW + s * 8 + tg + 4];
                mma_h(c[0][j], af[0], bf);
                mma_h(c[1][j], af[1], bf);
            }
        }
        __syncthreads();

        if (ch + 1 < NC) {
            uint32_t* An = As + (buf ^ 1) * G_TILE;
            uint32_t* Bn = Bs + (buf ^ 1) * G_TILE;
#pragma unroll
            for (int i = 0; i < 2; i++) {
                *(uint4*)&An[sAo[i]] = va[i];
                *(uint4*)&Bn[sAo[i]] = vb[i];
            }
            __syncthreads();
        }
    }

#pragma unroll
    for (int i = 0; i < 2; i++) {
        int row = m0 + wm + 16 * i + g;
#pragma unroll
        for (int j = 0; j < 8; j++) {
            int col = n0 + wn + 8 * j + 2 * tg;
            float2 bv = *(const float2*)(bias + col);
            float2 o0, o1;
            o0.x = c[i][j][0] + bv.x;  o0.y = c[i][j][1] + bv.y;
            o1.x = c[i][j][2] + bv.x;  o1.y = c[i][j][3] + bv.y;
            if (Cf != nullptr) {
                *(float2*)(Cf + (size_t)row * N + col) = o0;
                *(float2*)(Cf + (size_t)(row + 8) * N + col) = o1;
            }
            if (Ch != nullptr) {
                *(uint32_t*)(Ch + (size_t)row * N + col) = pack_h2(o0.x, o0.y);
                *(uint32_t*)(Ch + (size_t)(row + 8) * N + col) = pack_h2(o1.x, o1.y);
            }
            if (cache != nullptr && col >= CC) {
                int cc = col - CC;
                *(float2*)(cache + (size_t)row * (2 * CC) + cc) = o0;
                *(float2*)(cache + (size_t)(row + 8) * (2 * CC) + cc) = o1;
            }
        }
    }
}

// ---------------------------------------------------------------------------
// Flash attention, fp16 mma (causal). Grid: (B*H, T/128). 256 threads.
// smem (u32): Qs[128][68], Ks[64][68], Vt[128][36], Ps[128][36]
// ---------------------------------------------------------------------------
#define AQW 68
#define AVW 36
#define ATTN_SMEM_U32 (128*AQW + 64*AQW + 128*AVW + 128*AVW)
#define ATTN_SMEM_BYTES (ATTN_SMEM_U32 * 4)

__global__ __launch_bounds__(256)
void attn_h_kernel(const __half* __restrict__ qkv, __half* __restrict__ y) {
    extern __shared__ uint32_t smu[];
    uint32_t* Qs = smu;                   // [128][68]
    uint32_t* Ks = Qs + 128 * AQW;        // [64][68]
    uint32_t* Vt = Ks + 64 * AQW;         // [128][36]
    uint32_t* Ps = Vt + 128 * AVW;        // [128][36]

    const int tid  = threadIdx.x;
    const int wid  = tid >> 5;
    const int lane = tid & 31;
    const int g    = lane >> 2;
    const int tg   = lane & 3;
    const int bh   = blockIdx.x;
    const int b    = bh >> 4;
    const int h    = bh & 15;
    const int qt   = gridDim.y - 1 - blockIdx.y;
    const int q0   = qt * 128;
    const int wr0  = wid * 16;

    const float SCALE = 0.08838834764831845f;
    const int ROWU4 = QKV_N / 8;          // 768

    const uint4* qkv4 = (const uint4*)qkv;
    const size_t bbase = (size_t)b * TT * ROWU4;
    const int qoff = h * 16;
    const int koff = 256 + h * 16;
    const int voff = 512 + h * 16;

#pragma unroll
    for (int p = 0; p < 8; p++) {
        int i = tid + 256 * p;
        int r = i >> 4, c4 = i & 15;
        uint4 v = qkv4[bbase + (size_t)(q0 + r) * ROWU4 + qoff + c4];
        *(uint4*)&Qs[r * AQW + c4 * 4] = v;
    }

    float m_prev[2] = {-1e30f, -1e30f};
    float l_acc[2]  = {0.0f, 0.0f};
    float acc[16][4];
#pragma unroll
    for (int nj = 0; nj < 16; nj++)
#pragma unroll
        for (int q = 0; q < 4; q++) acc[nj][q] = 0.0f;

    const int ntiles = 2 * qt + 2;

    for (int kt = 0; kt < ntiles; ++kt) {
        const int k0 = kt * 64;
        __syncthreads();

#pragma unroll
        for (int p = 0; p < 4; p++) {
            int i = tid + 256 * p;
            int r = i >> 4, c4 = i & 15;
            uint4 v = qkv4[bbase + (size_t)(k0 + r) * ROWU4 + koff + c4];
            *(uint4*)&Ks[r * AQW + c4 * 4] = v;
        }
#pragma unroll
        for (int p = 0; p < 2; p++) {
            int t = tid + 256 * p;
            int pr = t & 31;
            int dc = t >> 5;
            union { uint4 v; unsigned short s[8]; } ua, ub;
            ua.v = qkv4[bbase + (size_t)(k0 + 2 * pr)     * ROWU4 + voff + dc];
            ub.v = qkv4[bbase + (size_t)(k0 + 2 * pr + 1) * ROWU4 + voff + dc];
#pragma unroll
            for (int j = 0; j < 8; j++)
                Vt[(dc * 8 + j) * AVW + pr] =
                    (uint32_t)ua.s[j] | ((uint32_t)ub.s[j] << 16);
        }
        __syncthreads();

        float cs[8][4];
#pragma unroll
        for (int j = 0; j < 8; j++)
#pragma unroll
            for (int q = 0; q < 4; q++) cs[j][q] = 0.0f;

#pragma unroll
        for (int s = 0; s < 8; s++) {
            uint32_t a[4];
            a[0] = Qs[(wr0 + g)     * AQW + s * 8 + tg];
            a[1] = Qs[(wr0 + g + 8) * AQW + s * 8 + tg];
            a[2] = Qs[(wr0 + g)     * AQW + s * 8 + tg + 4];
            a[3] = Qs[(wr0 + g + 8) * AQW + s * 8 + tg + 4];
#pragma unroll
            for (int j = 0; j < 8; j++) {
                uint32_t bf[2];
                bf[0] = Ks[(8 * j + g) * AQW + s * 8 + tg];
                bf[1] = Ks[(8 * j + g) * AQW + s * 8 + tg + 4];
                mma_h(cs[j], a, bf);
            }
        }

        const int gr0 = q0 + wr0 + g;
        const int gr1 = gr0 + 8;
        float mx0 = -1e30f, mx1 = -1e30f;
#pragma unroll
        for (int j = 0; j < 8; j++) {
            int gc0 = k0 + 8 * j + 2 * tg;
            int gc1 = gc0 + 1;
            float s0 = cs[j][0] * SCALE; if (gc0 > gr0) s0 = -1e30f;
            float s1 = cs[j][1] * SCALE; if (gc1 > gr0) s1 = -1e30f;
            float s2 = cs[j][2] * SCALE; if (gc0 > gr1) s2 = -1e30f;
            float s3 = cs[j][3] * SCALE; if (gc1 > gr1) s3 = -1e30f;
            cs[j][0] = s0; cs[j][1] = s1; cs[j][2] = s2; cs[j][3] = s3;
            mx0 = fmaxf(mx0, fmaxf(s0, s1));
            mx1 = fmaxf(mx1, fmaxf(s2, s3));
        }
        mx0 = fmaxf(mx0, __shfl_xor_sync(0xffffffffu, mx0, 1));
        mx0 = fmaxf(mx0, __shfl_xor_sync(0xffffffffu, mx0, 2));
        mx1 = fmaxf(mx1, __shfl_xor_sync(0xffffffffu, mx1, 1));
        mx1 = fmaxf(mx1, __shfl_xor_sync(0xffffffffu, mx1, 2));

        float mn0 = fmaxf(m_prev[0], mx0);
        float mn1 = fmaxf(m_prev[1], mx1);
        float f0 = __expf(m_prev[0] - mn0);
        float f1 = __expf(m_prev[1] - mn1);
        m_prev[0] = mn0; m_prev[1] = mn1;

        float ls0 = 0.0f, ls1 = 0.0f;
#pragma unroll
        for (int j = 0; j < 8; j++) {
            float p0 = __expf(cs[j][0] - mn0);
            float p1 = __expf(cs[j][1] - mn0);
            float p2 = __expf(cs[j][2] - mn1);
            float p3 = __expf(cs[j][3] - mn1);
            ls0 += p0 + p1;
            ls1 += p2 + p3;
            Ps[(wr0 + g)     * AVW + 4 * j + tg] = pack_h2(p0, p1);
            Ps[(wr0 + g + 8) * AVW + 4 * j + tg] = pack_h2(p2, p3);
        }
        ls0 += __shfl_xor_sync(0xffffffffu, ls0, 1);
        ls0 += __shfl_xor_sync(0xffffffffu, ls0, 2);
        ls1 += __shfl_xor_sync(0xffffffffu, ls1, 1);
        ls1 += __shfl_xor_sync(0xffffffffu, ls1, 2);
        l_acc[0] = l_acc[0] * f0 + ls0;
        l_acc[1] = l_acc[1] * f1 + ls1;

#pragma unroll
        for (int nj = 0; nj < 16; nj++) {
            acc[nj][0] *= f0; acc[nj][1] *= f0;
            acc[nj][2] *= f1; acc[nj][3] *= f1;
        }
        __syncwarp();

#pragma unroll
        for (int s = 0; s < 4; s++) {
            uint32_t a[4];
            a[0] = Ps[(wr0 + g)     * AVW + s * 8 + tg];
            a[1] = Ps[(wr0 + g + 8) * AVW + s * 8 + tg];
            a[2] = Ps[(wr0 + g)     * AVW + s * 8 + tg + 4];
            a[3] = Ps[(wr0 + g + 8) * AVW + s * 8 + tg + 4];
#pragma unroll
            for (int nj = 0; nj < 16; nj++) {
                uint32_t bf[2];
                bf[0] = Vt[(8 * nj + g) * AVW + s * 8 + tg];
                bf[1] = Vt[(8 * nj + g) * AVW + s * 8 + tg + 4];
                mma_h(acc[nj], a, bf);
            }
        }
        __syncwarp();
    }

    float inv0 = 1.0f / l_acc[0];
    float inv1 = 1.0f / l_acc[1];
    size_t row0 = (size_t)(b * TT + q0 + wr0 + g);
    size_t row1 = row0 + 8;
#pragma unroll
    for (int nj = 0; nj < 16; nj++) {
        int col = h * DH + 8 * nj + 2 * tg;
        *(uint32_t*)(y + row0 * CC + col) = pack_h2(acc[nj][0] * inv0, acc[nj][1] * inv0);
        *(uint32_t*)(y + row1 * CC + col) = pack_h2(acc[nj][2] * inv1, acc[nj][3] * inv1);
    }
}

// ---------------------------------------------------------------------------
extern "C" void kernel_launch(void* const* d_in, const int* in_sizes, int n_in,
                              void* d_out, int out_size) {
    (void)in_sizes; (void)n_in; (void)out_size;
    const float* x      = (const float*)d_in[0];
    const float* W_attn = (const float*)d_in[2];
    const float* b_attn = (const float*)d_in[3];
    const float* W_proj = (const float*)d_in[4];
    const float* b_proj = (const float*)d_in[5];

    float* out   = (float*)d_out;
    float* y_out = out;
    float* cache = out + (size_t)M_ROWS * CC;

    __half *xh, *qkvh, *yh, *wath, *wpth;
    cudaGetSymbolAddress((void**)&xh,   g_xh);
    cudaGetSymbolAddress((void**)&qkvh, g_qkvh);
    cudaGetSymbolAddress((void**)&yh,   g_yh);
    cudaGetSymbolAddress((void**)&wath, g_wath);
    cudaGetSymbolAddress((void**)&wpth, g_wpth);

    cudaFuncSetAttribute(h_gemm_kernel,
                         cudaFuncAttributeMaxDynamicSharedMemorySize, GEMM_SMEM);
    cudaFuncSetAttribute(attn_h_kernel,
                         cudaFuncAttributeMaxDynamicSharedMemorySize, ATTN_SMEM_BYTES);

    // 0) pre-pass conversions
    f2h_kernel<<<(int)((size_t)M_ROWS * CC / 4 / 256), 256>>>(x, xh);
    {
        dim3 blk(32, 8);
        trans_h_kernel<<<dim3(QKV_N / 32, CC / 32), blk>>>(W_attn, wath, CC, QKV_N);
        trans_h_kernel<<<dim3(CC / 32, CC / 32), blk>>>(W_proj, wpth, CC, CC);
    }
    // 1) qkv = x @ W_attn + b_attn -> qkv fp16 + fused f32 cache
    {
        dim3 grid(QKV_N / GBN, M_ROWS / GBM);   // (48, 32)
        h_gemm_kernel<<<grid, 256, GEMM_SMEM>>>(xh, wath, b_attn,
                                                nullptr, qkvh, cache,
                                                M_ROWS, QKV_N, CC);
    }
    // 2) flash attention fp16 -> yh
    {
        dim3 grid(BB * HH, TT / 128);           // (32, 16)
        attn_h_kernel<<<grid, 256, ATTN_SMEM_BYTES>>>(qkvh, yh);
    }
    // 3) y = yh @ W_proj + b_proj -> f32 out
    {
        dim3 grid(CC / GBN, M_ROWS / GBM);      // (16, 32)
        h_gemm_kernel<<<grid, 256, GEMM_SMEM>>>(yh, wpth, b_proj,
                                                y_out, nullptr, nullptr,
                                                M_ROWS, CC, CC);
    }
}

// round 7
// speedup vs baseline: 5.1637x; 1.1453x over previous
#include <cuda_runtime.h>
#include <cuda_fp16.h>
#include <cstdint>
#include <cstddef>

// Problem constants
#define BB 2
#define TT 2048
#define CC 2048
#define HH 16
#define DH 128
#define M_ROWS (BB*TT)          // 4096
#define QKV_N  (3*CC)           // 6144

// Scratch (allocation-free rule: __device__ globals)
__device__ __half g_xh  [(size_t)M_ROWS * CC];      // x fp16        16 MB
__device__ __half g_qkvh[(size_t)M_ROWS * QKV_N];   // qkv fp16      48 MB
__device__ __half g_yh  [(size_t)M_ROWS * CC];      // attn out fp16 16 MB
__device__ __half g_wath[(size_t)QKV_N * CC];       // W_attn^T fp16 24 MB
__device__ __half g_wpth[(size_t)CC * CC];          // W_proj^T fp16  8 MB

// ---------------------------------------------------------------------------
// PTX helpers (all plain sm_80+)
// ---------------------------------------------------------------------------
__device__ __forceinline__ void mma_h(float* c, const uint32_t* a, const uint32_t* b) {
    asm volatile(
        "mma.sync.aligned.m16n8k16.row.col.f32.f16.f16.f32 "
        "{%0,%1,%2,%3}, {%4,%5,%6,%7}, {%8,%9}, {%0,%1,%2,%3};"
        : "+f"(c[0]), "+f"(c[1]), "+f"(c[2]), "+f"(c[3])
        : "r"(a[0]), "r"(a[1]), "r"(a[2]), "r"(a[3]), "r"(b[0]), "r"(b[1]));
}

__device__ __forceinline__ uint32_t pack_h2(float lo, float hi) {
    __half2 h = __floats2half2_rn(lo, hi);
    return *(uint32_t*)&h;
}

__device__ __forceinline__ uint32_t smem_u32(const void* p) {
    uint32_t a;
    asm("{ .reg .u64 t; cvta.to.shared.u64 t, %1; cvt.u32.u64 %0, t; }"
        : "=r"(a) : "l"(p));
    return a;
}

__device__ __forceinline__ void ldsm_x4(uint32_t* r, uint32_t addr) {
    asm volatile("ldmatrix.sync.aligned.m8n8.x4.shared.b16 {%0,%1,%2,%3}, [%4];"
                 : "=r"(r[0]), "=r"(r[1]), "=r"(r[2]), "=r"(r[3]) : "r"(addr));
}

__device__ __forceinline__ void cp16(uint32_t saddr, const void* gaddr) {
    asm volatile("cp.async.cg.shared.global [%0], [%1], 16;"
                 :: "r"(saddr), "l"(gaddr));
}
#define CP_COMMIT() asm volatile("cp.async.commit_group;" ::: "memory")
#define CP_WAIT1()  asm volatile("cp.async.wait_group 1;" ::: "memory")
#define CP_WAIT0()  asm volatile("cp.async.wait_group 0;" ::: "memory")

// ---------------------------------------------------------------------------
// Pre-pass: f32 -> f16 convert
// ---------------------------------------------------------------------------
__global__ __launch_bounds__(256)
void f2h_kernel(const float* __restrict__ in, __half* __restrict__ out) {
    size_t i = (size_t)blockIdx.x * 256 + threadIdx.x;
    float4 v = ((const float4*)in)[i];
    uint2 o;
    o.x = pack_h2(v.x, v.y);
    o.y = pack_h2(v.z, v.w);
    ((uint2*)out)[i] = o;
}

// ---------------------------------------------------------------------------
// Pre-pass: transpose + convert: in [R][Cn] f32 -> out [Cn][R] f16
// ---------------------------------------------------------------------------
__global__ void trans_h_kernel(const float* __restrict__ in, __half* __restrict__ out,
                               int R, int Cn) {
    __shared__ float t[32][33];
    int bx = blockIdx.x * 32, by = blockIdx.y * 32;
    int tx = threadIdx.x, ty = threadIdx.y;   // (32, 8)
#pragma unroll
    for (int j = 0; j < 32; j += 8)
        t[ty + j][tx] = in[(size_t)(by + ty + j) * Cn + bx + tx];
    __syncthreads();
#pragma unroll
    for (int j = 0; j < 32; j += 8)
        out[(size_t)(bx + ty + j) * R + by + tx] = __float2half_rn(t[tx][ty + j]);
}

// ---------------------------------------------------------------------------
// fp16 GEMM:  C[M,N] = A[M,K]h @ Bt[N,K]h^T + bias[N]
// BM=BN=128, BK=32 halfs. 256 threads, 8 warps (4m x 2n), warp tile 32x64.
// cp.async 3-stage pipeline + ldmatrix fragments.
// smem rows: 16 u32 data + 4 pad (GROW=20) -> ldmatrix conflict-free.
// ---------------------------------------------------------------------------
#define GBM 128
#define GBN 128
#define GBK 32
#define GROW 20
#define G_TILE (128 * GROW)              // 2560 u32 per operand-stage
#define STAGES 3
#define GEMM_SMEM (2 * STAGES * G_TILE * 4)   // 61440 B

__global__ __launch_bounds__(256, 2)
void h_gemm_kernel(const __half* __restrict__ A, const __half* __restrict__ Bt,
                   const float* __restrict__ bias,
                   float* __restrict__ Cf, __half* __restrict__ Ch,
                   float* __restrict__ cache,
                   int M, int N, int K) {
    extern __shared__ uint32_t smu[];
    const uint32_t sbase = smem_u32(smu);
    const uint32_t sA = sbase;                            // [STAGES][G_TILE]
    const uint32_t sB = sbase + STAGES * G_TILE * 4;      // [STAGES][G_TILE]

    const int tid  = threadIdx.x;
    const int wid  = tid >> 5;
    const int lane = tid & 31;
    const int g    = lane >> 2;
    const int tg   = lane & 3;
    const int wm   = (wid & 3) * 32;
    const int wn   = (wid >> 2) * 64;
    const int m0   = blockIdx.y * GBM;
    const int n0   = blockIdx.x * GBN;
    const int rowu4 = K / 8;

    // cp.async coords: 2 chunks of 16B per operand per thread
    const uint4* gA[2]; const uint4* gB[2]; uint32_t so[2];
#pragma unroll
    for (int i = 0; i < 2; i++) {
        int idx = i * 256 + tid;
        int r = idx >> 2, c4 = idx & 3;
        gA[i] = (const uint4*)A + (size_t)(m0 + r) * rowu4 + c4;
        gB[i] = (const uint4*)Bt + (size_t)(n0 + r) * rowu4 + c4;
        so[i] = (uint32_t)(r * GROW + c4 * 4) * 4;
    }

    // ldmatrix lane addressing
    const int mrow = lane & 7;
    const int msel = lane >> 3;
    // A: row = wm + 16i + (msel&1)*8 + mrow ; colu = s*8 + (msel>>1)*4
    uint32_t aOff[2];
#pragma unroll
    for (int i = 0; i < 2; i++)
        aOff[i] = (uint32_t)(((wm + 16 * i + (msel & 1) * 8 + mrow) * GROW
                             + (msel >> 1) * 4) * 4);
    // B: row = wn + 16jj + (msel>>1)*8 + mrow ; colu = s*8 + (msel&1)*4
    uint32_t bOff[4];
#pragma unroll
    for (int jj = 0; jj < 4; jj++)
        bOff[jj] = (uint32_t)(((wn + 16 * jj + (msel >> 1) * 8 + mrow) * GROW
                              + (msel & 1) * 4) * 4);

    float c[2][8][4];
#pragma unroll
    for (int i = 0; i < 2; i++)
#pragma unroll
        for (int j = 0; j < 8; j++)
#pragma unroll
            for (int q = 0; q < 4; q++) c[i][j][q] = 0.0f;

    const int NC = K / GBK;   // chunks

    // Prologue: issue stages 0, 1
#pragma unroll
    for (int st = 0; st < 2; st++) {
        uint32_t aS = sA + st * G_TILE * 4;
        uint32_t bS = sB + st * G_TILE * 4;
#pragma unroll
        for (int i = 0; i < 2; i++) {
            cp16(aS + so[i], gA[i] + st * 4);
            cp16(bS + so[i], gB[i] + st * 4);
        }
        CP_COMMIT();
    }

    for (int ch = 0; ch < NC; ++ch) {
        if (ch + 1 < NC) { CP_WAIT1(); } else { CP_WAIT0(); }
        __syncthreads();   // chunk ch visible to all; stage (ch+2)%3 free

        if (ch + 2 < NC) {
            int st = (ch + 2) % STAGES;
            uint32_t aS = sA + st * G_TILE * 4;
            uint32_t bS = sB + st * G_TILE * 4;
#pragma unroll
            for (int i = 0; i < 2; i++) {
                cp16(aS + so[i], gA[i] + (ch + 2) * 4);
                cp16(bS + so[i], gB[i] + (ch + 2) * 4);
            }
            CP_COMMIT();
        }

        const int cur = ch % STAGES;
        const uint32_t aS = sA + cur * G_TILE * 4;
        const uint32_t bS = sB + cur * G_TILE * 4;

#pragma unroll
        for (int s = 0; s < 2; s++) {
            uint32_t a[2][4], bq[4][4];
#pragma unroll
            for (int i = 0; i < 2; i++)
                ldsm_x4(a[i], aS + aOff[i] + s * 32);
#pragma unroll
            for (int jj = 0; jj < 4; jj++)
                ldsm_x4(bq[jj], bS + bOff[jj] + s * 32);
#pragma unroll
            for (int i = 0; i < 2; i++)
#pragma unroll
                for (int jj = 0; jj < 4; jj++) {
                    mma_h(c[i][2 * jj],     a[i], &bq[jj][0]);
                    mma_h(c[i][2 * jj + 1], a[i], &bq[jj][2]);
                }
        }
    }

    // Epilogue
#pragma unroll
    for (int i = 0; i < 2; i++) {
        int row = m0 + wm + 16 * i + g;
#pragma unroll
        for (int j = 0; j < 8; j++) {
            int col = n0 + wn + 8 * j + 2 * tg;
            float2 bv = *(const float2*)(bias + col);
            float2 o0, o1;
            o0.x = c[i][j][0] + bv.x;  o0.y = c[i][j][1] + bv.y;
            o1.x = c[i][j][2] + bv.x;  o1.y = c[i][j][3] + bv.y;
            if (Cf != nullptr) {
                *(float2*)(Cf + (size_t)row * N + col) = o0;
                *(float2*)(Cf + (size_t)(row + 8) * N + col) = o1;
            }
            if (Ch != nullptr) {
                *(uint32_t*)(Ch + (size_t)row * N + col) = pack_h2(o0.x, o0.y);
                *(uint32_t*)(Ch + (size_t)(row + 8) * N + col) = pack_h2(o1.x, o1.y);
            }
            if (cache != nullptr && col >= CC) {
                int cc = col - CC;
                *(float2*)(cache + (size_t)row * (2 * CC) + cc) = o0;
                *(float2*)(cache + (size_t)(row + 8) * (2 * CC) + cc) = o1;
            }
        }
    }
}

// ---------------------------------------------------------------------------
// Flash attention, fp16 mma (causal). Grid: (B*H, T/128). 256 threads.
// smem (u32): Qs[128][68], Ks[64][68], Vt[128][36], Ps[128][36]
// ---------------------------------------------------------------------------
#define AQW 68
#define AVW 36
#define ATTN_SMEM_U32 (128*AQW + 64*AQW + 128*AVW + 128*AVW)
#define ATTN_SMEM_BYTES (ATTN_SMEM_U32 * 4)

__global__ __launch_bounds__(256)
void attn_h_kernel(const __half* __restrict__ qkv, __half* __restrict__ y) {
    extern __shared__ uint32_t smu[];
    uint32_t* Qs = smu;                   // [128][68]
    uint32_t* Ks = Qs + 128 * AQW;        // [64][68]
    uint32_t* Vt = Ks + 64 * AQW;         // [128][36]
    uint32_t* Ps = Vt + 128 * AVW;        // [128][36]

    const int tid  = threadIdx.x;
    const int wid  = tid >> 5;
    const int lane = tid & 31;
    const int g    = lane >> 2;
    const int tg   = lane & 3;
    const int bh   = blockIdx.x;
    const int b    = bh >> 4;
    const int h    = bh & 15;
    const int qt   = gridDim.y - 1 - blockIdx.y;
    const int q0   = qt * 128;
    const int wr0  = wid * 16;

    const float SCALE = 0.08838834764831845f;
    const int ROWU4 = QKV_N / 8;          // 768

    const uint4* qkv4 = (const uint4*)qkv;
    const size_t bbase = (size_t)b * TT * ROWU4;
    const int qoff = h * 16;
    const int koff = 256 + h * 16;
    const int voff = 512 + h * 16;

#pragma unroll
    for (int p = 0; p < 8; p++) {
        int i = tid + 256 * p;
        int r = i >> 4, c4 = i & 15;
        uint4 v = qkv4[bbase + (size_t)(q0 + r) * ROWU4 + qoff + c4];
        *(uint4*)&Qs[r * AQW + c4 * 4] = v;
    }

    float m_prev[2] = {-1e30f, -1e30f};
    float l_acc[2]  = {0.0f, 0.0f};
    float acc[16][4];
#pragma unroll
    for (int nj = 0; nj < 16; nj++)
#pragma unroll
        for (int q = 0; q < 4; q++) acc[nj][q] = 0.0f;

    const int ntiles = 2 * qt + 2;

    for (int kt = 0; kt < ntiles; ++kt) {
        const int k0 = kt * 64;
        __syncthreads();

#pragma unroll
        for (int p = 0; p < 4; p++) {
            int i = tid + 256 * p;
            int r = i >> 4, c4 = i & 15;
            uint4 v = qkv4[bbase + (size_t)(k0 + r) * ROWU4 + koff + c4];
            *(uint4*)&Ks[r * AQW + c4 * 4] = v;
        }
#pragma unroll
        for (int p = 0; p < 2; p++) {
            int t = tid + 256 * p;
            int pr = t & 31;
            int dc = t >> 5;
            union { uint4 v; unsigned short s[8]; } ua, ub;
            ua.v = qkv4[bbase + (size_t)(k0 + 2 * pr)     * ROWU4 + voff + dc];
            ub.v = qkv4[bbase + (size_t)(k0 + 2 * pr + 1) * ROWU4 + voff + dc];
#pragma unroll
            for (int j = 0; j < 8; j++)
                Vt[(dc * 8 + j) * AVW + pr] =
                    (uint32_t)ua.s[j] | ((uint32_t)ub.s[j] << 16);
        }
        __syncthreads();

        float cs[8][4];
#pragma unroll
        for (int j = 0; j < 8; j++)
#pragma unroll
            for (int q = 0; q < 4; q++) cs[j][q] = 0.0f;

#pragma unroll
        for (int s = 0; s < 8; s++) {
            uint32_t a[4];
            a[0] = Qs[(wr0 + g)     * AQW + s * 8 + tg];
            a[1] = Qs[(wr0 + g + 8) * AQW + s * 8 + tg];
            a[2] = Qs[(wr0 + g)     * AQW + s * 8 + tg + 4];
            a[3] = Qs[(wr0 + g + 8) * AQW + s * 8 + tg + 4];
#pragma unroll
            for (int j = 0; j < 8; j++) {
                uint32_t bf[2];
                bf[0] = Ks[(8 * j + g) * AQW + s * 8 + tg];
                bf[1] = Ks[(8 * j + g) * AQW + s * 8 + tg + 4];
                mma_h(cs[j], a, bf);
            }
        }

        const int gr0 = q0 + wr0 + g;
        const int gr1 = gr0 + 8;
        float mx0 = -1e30f, mx1 = -1e30f;
#pragma unroll
        for (int j = 0; j < 8; j++) {
            int gc0 = k0 + 8 * j + 2 * tg;
            int gc1 = gc0 + 1;
            float s0 = cs[j][0] * SCALE; if (gc0 > gr0) s0 = -1e30f;
            float s1 = cs[j][1] * SCALE; if (gc1 > gr0) s1 = -1e30f;
            float s2 = cs[j][2] * SCALE; if (gc0 > gr1) s2 = -1e30f;
            float s3 = cs[j][3] * SCALE; if (gc1 > gr1) s3 = -1e30f;
            cs[j][0] = s0; cs[j][1] = s1; cs[j][2] = s2; cs[j][3] = s3;
            mx0 = fmaxf(mx0, fmaxf(s0, s1));
            mx1 = fmaxf(mx1, fmaxf(s2, s3));
        }
        mx0 = fmaxf(mx0, __shfl_xor_sync(0xffffffffu, mx0, 1));
        mx0 = fmaxf(mx0, __shfl_xor_sync(0xffffffffu, mx0, 2));
        mx1 = fmaxf(mx1, __shfl_xor_sync(0xffffffffu, mx1, 1));
        mx1 = fmaxf(mx1, __shfl_xor_sync(0xffffffffu, mx1, 2));

        float mn0 = fmaxf(m_prev[0], mx0);
        float mn1 = fmaxf(m_prev[1], mx1);
        float f0 = __expf(m_prev[0] - mn0);
        float f1 = __expf(m_prev[1] - mn1);
        m_prev[0] = mn0; m_prev[1] = mn1;

        float ls0 = 0.0f, ls1 = 0.0f;
#pragma unroll
        for (int j = 0; j < 8; j++) {
            float p0 = __expf(cs[j][0] - mn0);
            float p1 = __expf(cs[j][1] - mn0);
            float p2 = __expf(cs[j][2] - mn1);
            float p3 = __expf(cs[j][3] - mn1);
            ls0 += p0 + p1;
            ls1 += p2 + p3;
            Ps[(wr0 + g)     * AVW + 4 * j + tg] = pack_h2(p0, p1);
            Ps[(wr0 + g + 8) * AVW + 4 * j + tg] = pack_h2(p2, p3);
        }
        ls0 += __shfl_xor_sync(0xffffffffu, ls0, 1);
        ls0 += __shfl_xor_sync(0xffffffffu, ls0, 2);
        ls1 += __shfl_xor_sync(0xffffffffu, ls1, 1);
        ls1 += __shfl_xor_sync(0xffffffffu, ls1, 2);
        l_acc[0] = l_acc[0] * f0 + ls0;
        l_acc[1] = l_acc[1] * f1 + ls1;

#pragma unroll
        for (int nj = 0; nj < 16; nj++) {
            acc[nj][0] *= f0; acc[nj][1] *= f0;
            acc[nj][2] *= f1; acc[nj][3] *= f1;
        }
        __syncwarp();

#pragma unroll
        for (int s = 0; s < 4; s++) {
            uint32_t a[4];
            a[0] = Ps[(wr0 + g)     * AVW + s * 8 + tg];
            a[1] = Ps[(wr0 + g + 8) * AVW + s * 8 + tg];
            a[2] = Ps[(wr0 + g)     * AVW + s * 8 + tg + 4];
            a[3] = Ps[(wr0 + g + 8) * AVW + s * 8 + tg + 4];
#pragma unroll
            for (int nj = 0; nj < 16; nj++) {
                uint32_t bf[2];
                bf[0] = Vt[(8 * nj + g) * AVW + s * 8 + tg];
                bf[1] = Vt[(8 * nj + g) * AVW + s * 8 + tg + 4];
                mma_h(acc[nj], a, bf);
            }
        }
        __syncwarp();
    }

    float inv0 = 1.0f / l_acc[0];
    float inv1 = 1.0f / l_acc[1];
    size_t row0 = (size_t)(b * TT + q0 + wr0 + g);
    size_t row1 = row0 + 8;
#pragma unroll
    for (int nj = 0; nj < 16; nj++) {
        int col = h * DH + 8 * nj + 2 * tg;
        *(uint32_t*)(y + row0 * CC + col) = pack_h2(acc[nj][0] * inv0, acc[nj][1] * inv0);
        *(uint32_t*)(y + row1 * CC + col) = pack_h2(acc[nj][2] * inv1, acc[nj][3] * inv1);
    }
}

// ---------------------------------------------------------------------------
extern "C" void kernel_launch(void* const* d_in, const int* in_sizes, int n_in,
                              void* d_out, int out_size) {
    (void)in_sizes; (void)n_in; (void)out_size;
    const float* x      = (const float*)d_in[0];
    const float* W_attn = (const float*)d_in[2];
    const float* b_attn = (const float*)d_in[3];
    const float* W_proj = (const float*)d_in[4];
    const float* b_proj = (const float*)d_in[5];

    float* out   = (float*)d_out;
    float* y_out = out;
    float* cache = out + (size_t)M_ROWS * CC;

    __half *xh, *qkvh, *yh, *wath, *wpth;
    cudaGetSymbolAddress((void**)&xh,   g_xh);
    cudaGetSymbolAddress((void**)&qkvh, g_qkvh);
    cudaGetSymbolAddress((void**)&yh,   g_yh);
    cudaGetSymbolAddress((void**)&wath, g_wath);
    cudaGetSymbolAddress((void**)&wpth, g_wpth);

    cudaFuncSetAttribute(h_gemm_kernel,
                         cudaFuncAttributeMaxDynamicSharedMemorySize, GEMM_SMEM);
    cudaFuncSetAttribute(attn_h_kernel,
                         cudaFuncAttributeMaxDynamicSharedMemorySize, ATTN_SMEM_BYTES);

    // 0) pre-pass conversions
    f2h_kernel<<<(int)((size_t)M_ROWS * CC / 4 / 256), 256>>>(x, xh);
    {
        dim3 blk(32, 8);
        trans_h_kernel<<<dim3(QKV_N / 32, CC / 32), blk>>>(W_attn, wath, CC, QKV_N);
        trans_h_kernel<<<dim3(CC / 32, CC / 32), blk>>>(W_proj, wpth, CC, CC);
    }
    // 1) qkv = x @ W_attn + b_attn -> qkv fp16 + fused f32 cache
    {
        dim3 grid(QKV_N / GBN, M_ROWS / GBM);   // (48, 32)
        h_gemm_kernel<<<grid, 256, GEMM_SMEM>>>(xh, wath, b_attn,
                                                nullptr, qkvh, cache,
                                                M_ROWS, QKV_N, CC);
    }
    // 2) flash attention fp16 -> yh
    {
        dim3 grid(BB * HH, TT / 128);           // (32, 16)
        attn_h_kernel<<<grid, 256, ATTN_SMEM_BYTES>>>(qkvh, yh);
    }
    // 3) y = yh @ W_proj + b_proj -> f32 out
    {
        dim3 grid(CC / GBN, M_ROWS / GBM);      // (16, 32)
        h_gemm_kernel<<<grid, 256, GEMM_SMEM>>>(yh, wpth, b_proj,
                                                y_out, nullptr, nullptr,
                                                M_ROWS, CC, CC);
    }
}